// round 15
// baseline (speedup 1.0000x reference)
#include <cuda_runtime.h>
#include <cuda_fp16.h>
#include <cstdint>

// ---------------------------------------------------------------------------
// FNO spectral block: B=2, H=1024, W=1024, C=32, modes rows {0..31,992..1023},
// cols 0..31.
// Stages A/D: warp-level fp16 mma.sync, single-fp16 operands (error budget
//   verified empirically: each rounding source adds ~2e-4 incoherent noise).
// Stages B/C: fp32 f32x2 with duplicated (rr,ii) complex operand layout ->
//   zero pack-movs in the inner loops.
// ---------------------------------------------------------------------------

typedef unsigned long long ull;

// ---- device scratch (allocation-free) ----
__device__ float g_EB4[1024 * 64 * 4];               // [h][k1i]: (c,-s, s,c)
__device__ float g_EC4[1024 * 64 * 4];               // [h][k1i]: (c, s,-s,c)/H
__device__ float g_Wc [32 * 64 * 32 * 2];            // combined w0*(w1|w2)
__device__ __half g_FB [64 * 1024];                  // fwd DFT [fcol][w] fp16
__device__ __half g_GD [1024 * 64];                  // inv DFT [w][fcol] fp16
__device__ float4 g_A2 [(size_t)2 * 32 * 1024 * 32]; // [b][c][h][k2] (rr,ii)
__device__ float g_Xp [32 * 32 * 64 * 32 * 2];       // [hq*2+b][c][k1i][k2]
__device__ float4 g_XW2[(size_t)2 * 32 * 64 * 32];   // [b][c][k1i][k2] (rr,ii)
__device__ __half g_Zh[(size_t)2 * 1024 * 32 * 64];  // Z fp16 [b][h][c][fcol]

// ---- packed fp32x2 helpers ----
__device__ __forceinline__ void fma2(ull& acc, ull a, ull b) {
    asm("fma.rn.f32x2 %0, %1, %2, %0;" : "+l"(acc) : "l"(a), "l"(b));
}
__device__ __forceinline__ float2 unpack2(ull v) {
    float2 r; asm("mov.b64 {%0, %1}, %2;" : "=f"(r.x), "=f"(r.y) : "l"(v)); return r;
}

// ---- mma.sync / ldmatrix helpers (no 'a'-suffix features) ----
__device__ __forceinline__ uint32_t smem_u32(const void* p) {
    uint32_t a;
    asm("{ .reg .u64 t; cvta.to.shared.u64 t, %1; cvt.u32.u64 %0, t; }" : "=r"(a) : "l"(p));
    return a;
}
__device__ __forceinline__ void mma_f16(float* d, const uint32_t* a, const uint32_t* b) {
    asm("mma.sync.aligned.m16n8k16.row.col.f32.f16.f16.f32 "
        "{%0,%1,%2,%3}, {%4,%5,%6,%7}, {%8,%9}, {%0,%1,%2,%3};"
        : "+f"(d[0]), "+f"(d[1]), "+f"(d[2]), "+f"(d[3])
        : "r"(a[0]), "r"(a[1]), "r"(a[2]), "r"(a[3]), "r"(b[0]), "r"(b[1]));
}
__device__ __forceinline__ void ldmx4(uint32_t* r, uint32_t addr) {
    asm volatile("ldmatrix.sync.aligned.m8n8.x4.shared.b16 {%0,%1,%2,%3}, [%4];"
                 : "=r"(r[0]), "=r"(r[1]), "=r"(r[2]), "=r"(r[3]) : "r"(addr));
}
__device__ __forceinline__ uint32_t f2h2(float a, float b) {
    __half2 h = __floats2half2_rn(a, b);
    return *(uint32_t*)&h;
}

// ---------------------------------------------------------------------------
// Init: exact integer mod-1024 phase + float sincospif.
// ---------------------------------------------------------------------------
__global__ void k_init_tables() {
    const int row = blockIdx.x;
    const int t = threadIdx.x;      // 0..63
    {
        const int k2 = t >> 1;
        const int r = (k2 * row) & 1023;
        float s, c;
        sincospif((float)r / 512.0f, &s, &c);
        const float vF = (t & 1) ? -s : c;
        const float sc = (k2 == 0 ? 1.0f : 2.0f) / 1024.0f;
        const float vG = (t & 1) ? (-sc * s) : (sc * c);
        g_FB[t * 1024 + row] = __float2half_rn(vF);
        g_GD[row * 64 + t]   = __float2half_rn(vG);
    }
    {
        const int k1i = t;
        const int k1 = (k1i < 32) ? k1i : (960 + k1i);
        const int r = (k1 * row) & 1023;
        float s, c;
        sincospif((float)r / 512.0f, &s, &c);
        float* eb = &g_EB4[(row * 64 + k1i) * 4];
        eb[0] = c;  eb[1] = -s;
        eb[2] = s;  eb[3] = c;
        const float inv = 1.0f / 1024.0f;
        float* ec = &g_EC4[(row * 64 + k1i) * 4];
        ec[0] = c * inv;   ec[1] = s * inv;
        ec[2] = -s * inv;  ec[3] = c * inv;
    }
}

__global__ void k_init_w(const float* __restrict__ w0r, const float* __restrict__ w0i,
                         const float* __restrict__ w1r, const float* __restrict__ w1i,
                         const float* __restrict__ w2r, const float* __restrict__ w2i) {
    const int idx = blockIdx.x * 256 + threadIdx.x;   // 65536
    const int k2 = idx & 31;
    const int k1i = (idx >> 5) & 63;
    const int c = idx >> 11;
    const float ar = w0r[c], ai = w0i[c];
    float br, bi;
    if (k1i < 32) { const int o = (c * 32 + k1i) * 32 + k2;        br = w1r[o]; bi = w1i[o]; }
    else          { const int o = (c * 32 + (k1i - 32)) * 32 + k2; br = w2r[o]; bi = w2i[o]; }
    g_Wc[idx * 2]     = ar * br - ai * bi;
    g_Wc[idx * 2 + 1] = ar * bi + ai * br;
}

// ---------------------------------------------------------------------------
// Stage A (HMMA fp16): CTA per (4h, b).  D[m=(hh,c)=128, n=fcol=64] =
//   sum_w x[h,w,c]*F[fcol,w].  K=1024 in 16 chunks of 64, single fp16.
//   Output: duplicated (rr,ii) float4 layout for kB.
// ---------------------------------------------------------------------------
__global__ void __launch_bounds__(128) kTA(const float* __restrict__ x) {
    __shared__ __align__(16) char XH[18432];   // 128 m x 72 halfs
    __shared__ __align__(16) char FH[9216];    // 64 f x 72 halfs
    const uint32_t XHb = smem_u32(XH), FHb = smem_u32(FH);
    const int hg = blockIdx.x, b = blockIdx.y;
    const int t = threadIdx.x, warp = t >> 5, lane = t & 31;
    const int h0 = hg * 4;
    const float* xb = x + (size_t)(b * 1024 + h0) * 32768;

    const int g = lane >> 3, r = lane & 7;
    const int a_m = ((g & 1) << 3) + r;
    const int a_k = (g >> 1) << 3;
    const int b_n = ((g >> 1) << 3) + r;
    const int b_k = (g & 1) << 3;

    float acc[2][8][4];
#pragma unroll
    for (int i = 0; i < 2; i++)
#pragma unroll
        for (int j = 0; j < 8; j++)
#pragma unroll
            for (int q = 0; q < 4; q++) acc[i][j][q] = 0.f;

    const int M0 = warp * 32;
    for (int kc = 0; kc < 16; kc++) {
        const int w0 = kc * 64;
        __syncthreads();
        // x: 4h x 64w x 32c -> fp16 [m=(hh,c)][k=w]
#pragma unroll
        for (int j = 0; j < 4; j++) {
            const int idx = t + j * 128;           // 512 = 4h*16wq*8c4
            const int c4 = idx & 7, wq = (idx >> 3) & 15, hh = idx >> 7;
            const float* p = xb + (size_t)hh * 32768 + (size_t)(w0 + 4 * wq) * 32 + c4 * 4;
            const float4 v0 = *(const float4*)p;
            const float4 v1 = *(const float4*)(p + 32);
            const float4 v2 = *(const float4*)(p + 64);
            const float4 v3 = *(const float4*)(p + 96);
            const float e0[4] = {v0.x, v0.y, v0.z, v0.w};
            const float e1[4] = {v1.x, v1.y, v1.z, v1.w};
            const float e2[4] = {v2.x, v2.y, v2.z, v2.w};
            const float e3[4] = {v3.x, v3.y, v3.z, v3.w};
#pragma unroll
            for (int i = 0; i < 4; i++) {
                const int m = hh * 32 + c4 * 4 + i;
                uint2 val;
                val.x = f2h2(e0[i], e1[i]);
                val.y = f2h2(e2[i], e3[i]);
                *(uint2*)(XH + m * 144 + wq * 8) = val;
            }
        }
        // F: 64 rows x 64 k halfs
#pragma unroll
        for (int j = 0; j < 4; j++) {
            const int idx = t + j * 128;           // 512 = 64f*8q
            const int f = idx >> 3, q = idx & 7;
            *(uint4*)(FH + f * 144 + q * 16) = *(const uint4*)&g_FB[f * 1024 + w0 + q * 8];
        }
        __syncthreads();
#pragma unroll
        for (int ks = 0; ks < 4; ks++) {
            const int K0 = ks * 16;
            uint32_t ah[2][4];
#pragma unroll
            for (int t2 = 0; t2 < 2; t2++)
                ldmx4(ah[t2], XHb + (uint32_t)((M0 + 16 * t2 + a_m) * 144 + (K0 + a_k) * 2));
#pragma unroll
            for (int jn = 0; jn < 4; jn++) {
                uint32_t bh[4];
                ldmx4(bh, FHb + (uint32_t)((jn * 16 + b_n) * 144 + (K0 + b_k) * 2));
#pragma unroll
                for (int t2 = 0; t2 < 2; t2++) {
                    mma_f16(acc[t2][2 * jn],     ah[t2], bh);
                    mma_f16(acc[t2][2 * jn + 1], ah[t2], bh + 2);
                }
            }
        }
    }
    // write duplicated layout: A2[b][c][h][k2] = (re,re,im,im)
    const int h = h0 + warp;
    const int cq = lane >> 2, k2b = lane & 3;
#pragma unroll
    for (int t2 = 0; t2 < 2; t2++)
#pragma unroll
        for (int j = 0; j < 8; j++) {
            const int c = 16 * t2 + cq;
            const int k2 = 4 * j + k2b;
            g_A2[(((size_t)b * 32 + c) * 1024 + h) * 32 + k2] =
                make_float4(acc[t2][j][0], acc[t2][j][0], acc[t2][j][1], acc[t2][j][1]);
            g_A2[(((size_t)b * 32 + c + 8) * 1024 + h) * 32 + k2] =
                make_float4(acc[t2][j][2], acc[t2][j][2], acc[t2][j][3], acc[t2][j][3]);
        }
}

// ---------------------------------------------------------------------------
// Stage B (fp32): 2 channels per CTA share the EB tile.  grid (16,16,2), 256t.
// Dup-layout A -> inner loop is pure LDS.128 + fma2 (no movs).
// Dynamic smem: As4 [2][32][32] f4 (32K) + EBs [32][64] f4 (32K) = 64K.
// ---------------------------------------------------------------------------
#define SMEM_KB 65536
__global__ void __launch_bounds__(256) kB() {
    extern __shared__ __align__(16) char sb_[];
    float4 (*As4)[32][32] = (float4 (*)[32][32])sb_;
    float4 (*EBs)[64]     = (float4 (*)[64])(sb_ + 32768);
    const int hq = blockIdx.x, cg = blockIdx.y, b = blockIdx.z;
    const int t = threadIdx.x, tb = t & 127, cl = t >> 7;
    const int k1l = tb & 15;
    const int k2g = (tb >> 4) * 4;
    ull acc[4][4] = {};

    for (int ch = 0; ch < 2; ch++) {
        const int h0c = hq * 64 + ch * 32;
        __syncthreads();
#pragma unroll
        for (int k = 0; k < 8; k++) {                 // 2048 float4
            const int idx = t + k * 256;
            const int c2 = idx >> 10, hh = (idx >> 5) & 31, k2 = idx & 31;
            As4[c2][hh][k2] =
                g_A2[((size_t)(b * 32 + cg * 2 + c2) * 1024 + h0c + hh) * 32 + k2];
        }
#pragma unroll
        for (int k = 0; k < 8; k++) {                 // 2048 float4
            const int idx = t + k * 256;
            const int hh = idx >> 6, k1 = idx & 63;
            EBs[hh][k1] = *(const float4*)&g_EB4[((h0c + hh) * 64 + k1) * 4];
        }
        __syncthreads();
#pragma unroll 4
        for (int hh = 0; hh < 32; hh++) {
            ull ar[4], ai[4];
#pragma unroll
            for (int j = 0; j < 4; j++) {
                const ulonglong2 a = *(const ulonglong2*)&As4[cl][hh][k2g + j];
                ar[j] = a.x;
                ai[j] = a.y;
            }
#pragma unroll
            for (int i = 0; i < 4; i++) {
                const ulonglong2 e = *(const ulonglong2*)&EBs[hh][k1l + 16 * i];
#pragma unroll
                for (int j = 0; j < 4; j++) { fma2(acc[i][j], ar[j], e.x); fma2(acc[i][j], ai[j], e.y); }
            }
        }
    }
    const int c = cg * 2 + cl;
#pragma unroll
    for (int i = 0; i < 4; i++) {
        const int k1i = k1l + 16 * i;
#pragma unroll
        for (int j = 0; j < 4; j++)
            *(float2*)&g_Xp[(size_t)((((hq * 2 + b) * 32 + c) * 64 + k1i) * 32 + (k2g + j)) * 2]
                = unpack2(acc[i][j]);
    }
}

// Reduce 16 h-slice partials, apply weights, emit duplicated (rr,ii) layout.
__global__ void k_reduce_w() {
    const int id = blockIdx.x * 256 + threadIdx.x;   // 131072
    const int k2 = id & 31, k1i = (id >> 5) & 63, c = (id >> 11) & 31, b = id >> 16;
    float xr = 0.f, xi = 0.f;
#pragma unroll
    for (int hq = 0; hq < 16; hq++) {
        const float2 p = *(const float2*)
            &g_Xp[(size_t)((((hq * 2 + b) * 32 + c) * 64 + k1i) * 32 + k2) * 2];
        xr += p.x; xi += p.y;
    }
    const int wci = ((c << 6) + k1i) * 32 + k2;
    const float wr = g_Wc[wci * 2], wi = g_Wc[wci * 2 + 1];
    const float orr = xr * wr - xi * wi, oii = xr * wi + xi * wr;
    g_XW2[((size_t)(b * 32 + c) * 64 + k1i) * 32 + k2] = make_float4(orr, orr, oii, oii);
}

// ---------------------------------------------------------------------------
// Stage C (fp32): 2 channels per CTA; emits fp16 Z.  grid (32,16,2), 256t.
// Dynamic smem: XWs4 [2][64][32] f4 (64K) + ECs [32][17] f4 (8.7K) = 74240 B.
// ---------------------------------------------------------------------------
#define SMEM_KC 74240
__global__ void __launch_bounds__(256) kC() {
    extern __shared__ __align__(16) char sc_[];
    float4 (*XWs4)[64][32] = (float4 (*)[64][32])sc_;
    float4 (*ECs)[17]      = (float4 (*)[17])(sc_ + 65536);
    const int hc = blockIdx.x, cg = blockIdx.y, b = blockIdx.z;
    const int h0 = hc * 32;
    const int t = threadIdx.x, tb = t & 127, cl = t >> 7;
    const int hl = tb & 15;
    const int k2g = (tb >> 4) * 4;
    ull acc[2][4] = {};
#pragma unroll
    for (int k = 0; k < 16; k++) {                    // 4096 float4
        const int idx = t + k * 256;
        const int c2 = idx >> 11, k1 = (idx >> 5) & 63, k2 = idx & 31;
        XWs4[c2][k1][k2] = g_XW2[((size_t)(b * 32 + cg * 2 + c2) * 64 + k1) * 32 + k2];
    }
    for (int kc = 0; kc < 4; kc++) {
        __syncthreads();
#pragma unroll
        for (int k = 0; k < 2; k++) {
            const int idx = t + k * 256;
            const int hh = idx >> 4, kk = idx & 15;
            ECs[hh][kk] = *(const float4*)&g_EC4[((h0 + hh) * 64 + kc * 16 + kk) * 4];
        }
        __syncthreads();
#pragma unroll 4
        for (int kk = 0; kk < 16; kk++) {
            const int k1 = kc * 16 + kk;
            ull xr[4], xi[4];
#pragma unroll
            for (int j = 0; j < 4; j++) {
                const ulonglong2 a = *(const ulonglong2*)&XWs4[cl][k1][k2g + j];
                xr[j] = a.x;
                xi[j] = a.y;
            }
#pragma unroll
            for (int i = 0; i < 2; i++) {
                const ulonglong2 e = *(const ulonglong2*)&ECs[hl + 16 * i][kk];
#pragma unroll
                for (int j = 0; j < 4; j++) { fma2(acc[i][j], xr[j], e.x); fma2(acc[i][j], xi[j], e.y); }
            }
        }
    }
    const int c = cg * 2 + cl;
#pragma unroll
    for (int i = 0; i < 2; i++) {
        const int h = h0 + hl + 16 * i;
#pragma unroll
        for (int j = 0; j < 4; j++) {
            const float2 v = unpack2(acc[i][j]);
            const size_t o = (((size_t)b * 1024 + h) * 32 + c) * 64 + 2 * (k2g + j);
            *(uint32_t*)&g_Zh[o] = f2h2(v.x, v.y);
        }
    }
}

// ---------------------------------------------------------------------------
// Stage D (HMMA fp16): CTA per (wb=128w, hg=32h, b).  Per h:
//   y[m=w=128, n=c=32] = sum_f GD[w,f]*Z[c,f], K=64, single fp16.
// ---------------------------------------------------------------------------
__global__ void __launch_bounds__(128) kTD(float* __restrict__ y) {
    __shared__ __align__(16) char GH[18432];
    __shared__ __align__(16) char ZH[4608];
    const uint32_t GHb = smem_u32(GH), ZHb = smem_u32(ZH);
    const int wb = blockIdx.x, hg = blockIdx.y, b = blockIdx.z;
    const int t = threadIdx.x, warp = t >> 5, lane = t & 31;

    const int g = lane >> 3, r = lane & 7;
    const int a_m = ((g & 1) << 3) + r;
    const int a_k = (g >> 1) << 3;
    const int b_n = ((g >> 1) << 3) + r;
    const int b_k = (g & 1) << 3;

#pragma unroll
    for (int j = 0; j < 8; j++) {
        const int idx = t + j * 128;
        const int row = idx >> 3, q = idx & 7;
        *(uint4*)(GH + row * 144 + q * 16) = *(const uint4*)&g_GD[(wb * 128 + row) * 64 + q * 8];
    }
    __syncthreads();

    const int M0 = warp * 32;
    uint32_t gh[4][2][4];
#pragma unroll
    for (int ks = 0; ks < 4; ks++)
#pragma unroll
        for (int t2 = 0; t2 < 2; t2++)
            ldmx4(gh[ks][t2],
                  GHb + (uint32_t)((M0 + 16 * t2 + a_m) * 144 + (ks * 16 + a_k) * 2));

    const int cq = lane >> 2, f2 = (lane & 3) * 2;
    for (int hh = 0; hh < 32; hh++) {
        const int h = hg * 32 + hh;
        const size_t zb = (size_t)(b * 1024 + h) * 2048;
        __syncthreads();
#pragma unroll
        for (int j = 0; j < 2; j++) {                 // 256 uint4
            const int idx = t + j * 128;
            const int row = idx >> 3, q = idx & 7;
            *(uint4*)(ZH + row * 144 + q * 16) = *(const uint4*)&g_Zh[zb + row * 64 + q * 8];
        }
        __syncthreads();
        float acc[2][4][4];
#pragma unroll
        for (int i = 0; i < 2; i++)
#pragma unroll
            for (int j = 0; j < 4; j++)
#pragma unroll
                for (int q = 0; q < 4; q++) acc[i][j][q] = 0.f;
#pragma unroll
        for (int ks = 0; ks < 4; ks++) {
#pragma unroll
            for (int jn = 0; jn < 2; jn++) {
                uint32_t bh[4];
                ldmx4(bh, ZHb + (uint32_t)((jn * 16 + b_n) * 144 + (ks * 16 + b_k) * 2));
#pragma unroll
                for (int t2 = 0; t2 < 2; t2++) {
                    mma_f16(acc[t2][2 * jn],     gh[ks][t2], bh);
                    mma_f16(acc[t2][2 * jn + 1], gh[ks][t2], bh + 2);
                }
            }
        }
        float* yb = y + (size_t)(b * 1024 + h) * 32768;
#pragma unroll
        for (int t2 = 0; t2 < 2; t2++)
#pragma unroll
            for (int j = 0; j < 4; j++) {
                const int w = wb * 128 + M0 + 16 * t2 + cq;
                const int c = 8 * j + f2;
                *(float2*)&yb[(size_t)w * 32 + c] =
                    make_float2(acc[t2][j][0], acc[t2][j][1]);
                *(float2*)&yb[(size_t)(w + 8) * 32 + c] =
                    make_float2(acc[t2][j][2], acc[t2][j][3]);
            }
    }
}

// ---------------------------------------------------------------------------
extern "C" void kernel_launch(void* const* d_in, const int* in_sizes, int n_in,
                              void* d_out, int out_size) {
    const float* x   = (const float*)d_in[0];
    const float* w0r = (const float*)d_in[1];
    const float* w0i = (const float*)d_in[2];
    const float* w1r = (const float*)d_in[3];
    const float* w1i = (const float*)d_in[4];
    const float* w2r = (const float*)d_in[5];
    const float* w2i = (const float*)d_in[6];
    float* y = (float*)d_out;

    cudaFuncSetAttribute(kB, cudaFuncAttributeMaxDynamicSharedMemorySize, SMEM_KB);
    cudaFuncSetAttribute(kC, cudaFuncAttributeMaxDynamicSharedMemorySize, SMEM_KC);

    k_init_tables<<<1024, 64>>>();
    k_init_w<<<256, 256>>>(w0r, w0i, w1r, w1i, w2r, w2i);
    kTA<<<dim3(256, 2), 128>>>(x);
    kB<<<dim3(16, 16, 2), 256, SMEM_KB>>>();
    k_reduce_w<<<512, 256>>>();
    kC<<<dim3(32, 16, 2), 256, SMEM_KC>>>();
    kTD<<<dim3(8, 32, 2), 128>>>(y);
}

// round 16
// speedup vs baseline: 1.0800x; 1.0800x over previous
#include <cuda_runtime.h>
#include <cuda_fp16.h>
#include <cstdint>

// ---------------------------------------------------------------------------
// FNO spectral block: B=2, H=1024, W=1024, C=32, modes rows {0..31,992..1023},
// cols 0..31.
// Stages A/D: warp-level fp16 mma.sync, single-fp16 operands everywhere
//   (each rounding source ~2e-4 incoherent noise; budget verified R14/R15).
// Stages B/C: fp32 f32x2, compact float2 layouts (R14 design — dup layout
//   regressed in R15: kB is LDS-bandwidth bound, not mov-issue bound).
// ---------------------------------------------------------------------------

typedef unsigned long long ull;

// ---- device scratch (allocation-free) ----
__device__ float g_EB4[1024 * 64 * 4];               // [h][k1i]: (c,-s, s,c)
__device__ float g_EC4[1024 * 64 * 4];               // [h][k1i]: (c, s,-s,c)/H
__device__ float g_Wc [32 * 64 * 32 * 2];            // combined w0*(w1|w2)
__device__ __half g_FB [64 * 1024];                  // fwd DFT [fcol][w] fp16
__device__ __half g_GD [1024 * 64];                  // inv DFT [w][fcol] fp16
__device__ float g_A  [(size_t)2 * 32 * 1024 * 64];  // [b][c][h][fcol]
__device__ float g_Xp [32 * 32 * 64 * 32 * 2];       // [hq*2+b][c][k1i][k2]
__device__ float g_XW [(size_t)2 * 32 * 64 * 64];    // [b][c][k1i][2k2]
__device__ __half g_Zh[(size_t)2 * 1024 * 32 * 64];  // Z fp16 [b][h][c][fcol]

// ---- packed fp32x2 helpers ----
__device__ __forceinline__ void fma2(ull& acc, ull a, ull b) {
    asm("fma.rn.f32x2 %0, %1, %2, %0;" : "+l"(acc) : "l"(a), "l"(b));
}
__device__ __forceinline__ ull pack2(float x, float y) {
    ull r; asm("mov.b64 %0, {%1, %2};" : "=l"(r) : "f"(x), "f"(y)); return r;
}
__device__ __forceinline__ float2 unpack2(ull v) {
    float2 r; asm("mov.b64 {%0, %1}, %2;" : "=f"(r.x), "=f"(r.y) : "l"(v)); return r;
}

// ---- mma.sync / ldmatrix helpers (no 'a'-suffix features) ----
__device__ __forceinline__ uint32_t smem_u32(const void* p) {
    uint32_t a;
    asm("{ .reg .u64 t; cvta.to.shared.u64 t, %1; cvt.u32.u64 %0, t; }" : "=r"(a) : "l"(p));
    return a;
}
__device__ __forceinline__ void mma_f16(float* d, const uint32_t* a, const uint32_t* b) {
    asm("mma.sync.aligned.m16n8k16.row.col.f32.f16.f16.f32 "
        "{%0,%1,%2,%3}, {%4,%5,%6,%7}, {%8,%9}, {%0,%1,%2,%3};"
        : "+f"(d[0]), "+f"(d[1]), "+f"(d[2]), "+f"(d[3])
        : "r"(a[0]), "r"(a[1]), "r"(a[2]), "r"(a[3]), "r"(b[0]), "r"(b[1]));
}
__device__ __forceinline__ void ldmx4(uint32_t* r, uint32_t addr) {
    asm volatile("ldmatrix.sync.aligned.m8n8.x4.shared.b16 {%0,%1,%2,%3}, [%4];"
                 : "=r"(r[0]), "=r"(r[1]), "=r"(r[2]), "=r"(r[3]) : "r"(addr));
}
__device__ __forceinline__ uint32_t f2h2(float a, float b) {
    __half2 h = __floats2half2_rn(a, b);
    return *(uint32_t*)&h;
}

// ---------------------------------------------------------------------------
// Init: exact integer mod-1024 phase + float sincospif.
// ---------------------------------------------------------------------------
__global__ void k_init_tables() {
    const int row = blockIdx.x;
    const int t = threadIdx.x;      // 0..63
    {
        const int k2 = t >> 1;
        const int r = (k2 * row) & 1023;
        float s, c;
        sincospif((float)r / 512.0f, &s, &c);
        const float vF = (t & 1) ? -s : c;
        const float sc = (k2 == 0 ? 1.0f : 2.0f) / 1024.0f;
        const float vG = (t & 1) ? (-sc * s) : (sc * c);
        g_FB[t * 1024 + row] = __float2half_rn(vF);
        g_GD[row * 64 + t]   = __float2half_rn(vG);
    }
    {
        const int k1i = t;
        const int k1 = (k1i < 32) ? k1i : (960 + k1i);
        const int r = (k1 * row) & 1023;
        float s, c;
        sincospif((float)r / 512.0f, &s, &c);
        float* eb = &g_EB4[(row * 64 + k1i) * 4];
        eb[0] = c;  eb[1] = -s;
        eb[2] = s;  eb[3] = c;
        const float inv = 1.0f / 1024.0f;
        float* ec = &g_EC4[(row * 64 + k1i) * 4];
        ec[0] = c * inv;   ec[1] = s * inv;
        ec[2] = -s * inv;  ec[3] = c * inv;
    }
}

__global__ void k_init_w(const float* __restrict__ w0r, const float* __restrict__ w0i,
                         const float* __restrict__ w1r, const float* __restrict__ w1i,
                         const float* __restrict__ w2r, const float* __restrict__ w2i) {
    const int idx = blockIdx.x * 256 + threadIdx.x;   // 65536
    const int k2 = idx & 31;
    const int k1i = (idx >> 5) & 63;
    const int c = idx >> 11;
    const float ar = w0r[c], ai = w0i[c];
    float br, bi;
    if (k1i < 32) { const int o = (c * 32 + k1i) * 32 + k2;        br = w1r[o]; bi = w1i[o]; }
    else          { const int o = (c * 32 + (k1i - 32)) * 32 + k2; br = w2r[o]; bi = w2i[o]; }
    g_Wc[idx * 2]     = ar * br - ai * bi;
    g_Wc[idx * 2 + 1] = ar * bi + ai * br;
}

// ---------------------------------------------------------------------------
// Stage A (HMMA fp16): CTA per (4h, b).  D[m=(hh,c)=128, n=fcol=64] =
//   sum_w x[h,w,c]*F[fcol,w].  K=1024 in 16 chunks of 64, single fp16.
// ---------------------------------------------------------------------------
__global__ void __launch_bounds__(128) kTA(const float* __restrict__ x) {
    __shared__ __align__(16) char XH[18432];   // 128 m x 72 halfs
    __shared__ __align__(16) char FH[9216];    // 64 f x 72 halfs
    const uint32_t XHb = smem_u32(XH), FHb = smem_u32(FH);
    const int hg = blockIdx.x, b = blockIdx.y;
    const int t = threadIdx.x, warp = t >> 5, lane = t & 31;
    const int h0 = hg * 4;
    const float* xb = x + (size_t)(b * 1024 + h0) * 32768;

    const int g = lane >> 3, r = lane & 7;
    const int a_m = ((g & 1) << 3) + r;
    const int a_k = (g >> 1) << 3;
    const int b_n = ((g >> 1) << 3) + r;
    const int b_k = (g & 1) << 3;

    float acc[2][8][4];
#pragma unroll
    for (int i = 0; i < 2; i++)
#pragma unroll
        for (int j = 0; j < 8; j++)
#pragma unroll
            for (int q = 0; q < 4; q++) acc[i][j][q] = 0.f;

    const int M0 = warp * 32;
    for (int kc = 0; kc < 16; kc++) {
        const int w0 = kc * 64;
        __syncthreads();
        // x: 4h x 64w x 32c -> fp16 [m=(hh,c)][k=w]
#pragma unroll
        for (int j = 0; j < 4; j++) {
            const int idx = t + j * 128;           // 512 = 4h*16wq*8c4
            const int c4 = idx & 7, wq = (idx >> 3) & 15, hh = idx >> 7;
            const float* p = xb + (size_t)hh * 32768 + (size_t)(w0 + 4 * wq) * 32 + c4 * 4;
            const float4 v0 = *(const float4*)p;
            const float4 v1 = *(const float4*)(p + 32);
            const float4 v2 = *(const float4*)(p + 64);
            const float4 v3 = *(const float4*)(p + 96);
            const float e0[4] = {v0.x, v0.y, v0.z, v0.w};
            const float e1[4] = {v1.x, v1.y, v1.z, v1.w};
            const float e2[4] = {v2.x, v2.y, v2.z, v2.w};
            const float e3[4] = {v3.x, v3.y, v3.z, v3.w};
#pragma unroll
            for (int i = 0; i < 4; i++) {
                const int m = hh * 32 + c4 * 4 + i;
                uint2 val;
                val.x = f2h2(e0[i], e1[i]);
                val.y = f2h2(e2[i], e3[i]);
                *(uint2*)(XH + m * 144 + wq * 8) = val;
            }
        }
        // F: 64 rows x 64 k halfs
#pragma unroll
        for (int j = 0; j < 4; j++) {
            const int idx = t + j * 128;           // 512 = 64f*8q
            const int f = idx >> 3, q = idx & 7;
            *(uint4*)(FH + f * 144 + q * 16) = *(const uint4*)&g_FB[f * 1024 + w0 + q * 8];
        }
        __syncthreads();
#pragma unroll
        for (int ks = 0; ks < 4; ks++) {
            const int K0 = ks * 16;
            uint32_t ah[2][4];
#pragma unroll
            for (int t2 = 0; t2 < 2; t2++)
                ldmx4(ah[t2], XHb + (uint32_t)((M0 + 16 * t2 + a_m) * 144 + (K0 + a_k) * 2));
#pragma unroll
            for (int jn = 0; jn < 4; jn++) {
                uint32_t bh[4];
                ldmx4(bh, FHb + (uint32_t)((jn * 16 + b_n) * 144 + (K0 + b_k) * 2));
#pragma unroll
                for (int t2 = 0; t2 < 2; t2++) {
                    mma_f16(acc[t2][2 * jn],     ah[t2], bh);
                    mma_f16(acc[t2][2 * jn + 1], ah[t2], bh + 2);
                }
            }
        }
    }
    const int h = h0 + warp;
    const int cq = lane >> 2, f2 = (lane & 3) * 2;
#pragma unroll
    for (int t2 = 0; t2 < 2; t2++)
#pragma unroll
        for (int j = 0; j < 8; j++) {
            const int c = 16 * t2 + cq;
            const int f = 8 * j + f2;
            *(float2*)&g_A[(((size_t)b * 32 + c) * 1024 + h) * 64 + f] =
                make_float2(acc[t2][j][0], acc[t2][j][1]);
            *(float2*)&g_A[(((size_t)b * 32 + c + 8) * 1024 + h) * 64 + f] =
                make_float2(acc[t2][j][2], acc[t2][j][3]);
        }
}

// ---------------------------------------------------------------------------
// Stage B (fp32): 2 channels per CTA share the EB tile.  grid (16,16,2), 256t.
// ---------------------------------------------------------------------------
__global__ void __launch_bounds__(256) kB() {
    const int hq = blockIdx.x, cg = blockIdx.y, b = blockIdx.z;
    __shared__ __align__(16) float2 As[2][32][32];
    __shared__ __align__(16) float4 EBs[32][64];
    const int t = threadIdx.x, tb = t & 127, cl = t >> 7;
    const int k1l = tb & 15;
    const int k2g = (tb >> 4) * 4;
    ull acc[4][4] = {};

    for (int ch = 0; ch < 2; ch++) {
        const int h0c = hq * 64 + ch * 32;
        __syncthreads();
#pragma unroll
        for (int k = 0; k < 8; k++) {
            const int idx = t + k * 256;
            const int c2 = idx >> 10, hh = (idx >> 5) & 31, k2 = idx & 31;
            As[c2][hh][k2] = *(const float2*)
                &g_A[(((size_t)(b * 32 + cg * 2 + c2)) * 1024 + h0c + hh) * 64 + 2 * k2];
        }
#pragma unroll
        for (int k = 0; k < 8; k++) {
            const int idx = t + k * 256;
            const int hh = idx >> 6, k1 = idx & 63;
            EBs[hh][k1] = *(const float4*)&g_EB4[((h0c + hh) * 64 + k1) * 4];
        }
        __syncthreads();
#pragma unroll 4
        for (int hh = 0; hh < 32; hh++) {
            ull ar[4], ai[4];
#pragma unroll
            for (int j = 0; j < 4; j++) {
                const float2 a = As[cl][hh][k2g + j];
                ar[j] = pack2(a.x, a.x);
                ai[j] = pack2(a.y, a.y);
            }
#pragma unroll
            for (int i = 0; i < 4; i++) {
                const ulonglong2 e = *(const ulonglong2*)&EBs[hh][k1l + 16 * i];
#pragma unroll
                for (int j = 0; j < 4; j++) { fma2(acc[i][j], ar[j], e.x); fma2(acc[i][j], ai[j], e.y); }
            }
        }
    }
    const int c = cg * 2 + cl;
#pragma unroll
    for (int i = 0; i < 4; i++) {
        const int k1i = k1l + 16 * i;
#pragma unroll
        for (int j = 0; j < 4; j++)
            *(float2*)&g_Xp[(size_t)((((hq * 2 + b) * 32 + c) * 64 + k1i) * 32 + (k2g + j)) * 2]
                = unpack2(acc[i][j]);
    }
}

// Reduce 16 h-slice partials and apply combined weights.
__global__ void k_reduce_w() {
    const int id = blockIdx.x * 256 + threadIdx.x;   // 131072
    const int k2 = id & 31, k1i = (id >> 5) & 63, c = (id >> 11) & 31, b = id >> 16;
    float xr = 0.f, xi = 0.f;
#pragma unroll
    for (int hq = 0; hq < 16; hq++) {
        const float2 p = *(const float2*)
            &g_Xp[(size_t)((((hq * 2 + b) * 32 + c) * 64 + k1i) * 32 + k2) * 2];
        xr += p.x; xi += p.y;
    }
    const int wci = ((c << 6) + k1i) * 32 + k2;
    const float wr = g_Wc[wci * 2], wi = g_Wc[wci * 2 + 1];
    const float2 o = make_float2(xr * wr - xi * wi, xr * wi + xi * wr);
    *(float2*)&g_XW[((size_t)(b * 32 + c) * 64 + k1i) * 64 + 2 * k2] = o;
}

// ---------------------------------------------------------------------------
// Stage C (fp32): 2 channels per CTA; emits fp16 Z.  grid (32,16,2), 256t.
// ---------------------------------------------------------------------------
__global__ void __launch_bounds__(256) kC() {
    const int hc = blockIdx.x, cg = blockIdx.y, b = blockIdx.z;
    const int h0 = hc * 32;
    __shared__ __align__(16) float2 XWs[2][64][33];
    __shared__ __align__(16) float4 ECs[32][17];
    const int t = threadIdx.x, tb = t & 127, cl = t >> 7;
    const int hl = tb & 15;
    const int k2g = (tb >> 4) * 4;
    ull acc[2][4] = {};
#pragma unroll
    for (int k = 0; k < 16; k++) {
        const int idx = t + k * 256;
        const int c2 = idx >> 11, k1 = (idx >> 5) & 63, k2 = idx & 31;
        XWs[c2][k1][k2] = *(const float2*)
            &g_XW[((size_t)(b * 32 + cg * 2 + c2) * 64 + k1) * 64 + 2 * k2];
    }
    for (int kc = 0; kc < 4; kc++) {
        __syncthreads();
#pragma unroll
        for (int k = 0; k < 2; k++) {
            const int idx = t + k * 256;
            const int hh = idx >> 4, kk = idx & 15;
            ECs[hh][kk] = *(const float4*)&g_EC4[((h0 + hh) * 64 + kc * 16 + kk) * 4];
        }
        __syncthreads();
#pragma unroll 4
        for (int kk = 0; kk < 16; kk++) {
            const int k1 = kc * 16 + kk;
            ull xr[4], xi[4];
#pragma unroll
            for (int j = 0; j < 4; j++) {
                const float2 xw = XWs[cl][k1][k2g + j];
                xr[j] = pack2(xw.x, xw.x);
                xi[j] = pack2(xw.y, xw.y);
            }
#pragma unroll
            for (int i = 0; i < 2; i++) {
                const ulonglong2 e = *(const ulonglong2*)&ECs[hl + 16 * i][kk];
#pragma unroll
                for (int j = 0; j < 4; j++) { fma2(acc[i][j], xr[j], e.x); fma2(acc[i][j], xi[j], e.y); }
            }
        }
    }
    const int c = cg * 2 + cl;
#pragma unroll
    for (int i = 0; i < 2; i++) {
        const int h = h0 + hl + 16 * i;
#pragma unroll
        for (int j = 0; j < 4; j++) {
            const float2 v = unpack2(acc[i][j]);
            const size_t o = (((size_t)b * 1024 + h) * 32 + c) * 64 + 2 * (k2g + j);
            *(uint32_t*)&g_Zh[o] = f2h2(v.x, v.y);
        }
    }
}

// ---------------------------------------------------------------------------
// Stage D (HMMA fp16): CTA per (wb=128w, hg=32h, b).  Per h:
//   y[m=w=128, n=c=32] = sum_f GD[w,f]*Z[c,f], K=64, single fp16.
// ---------------------------------------------------------------------------
__global__ void __launch_bounds__(128) kTD(float* __restrict__ y) {
    __shared__ __align__(16) char GH[18432];
    __shared__ __align__(16) char ZH[4608];
    const uint32_t GHb = smem_u32(GH), ZHb = smem_u32(ZH);
    const int wb = blockIdx.x, hg = blockIdx.y, b = blockIdx.z;
    const int t = threadIdx.x, warp = t >> 5, lane = t & 31;

    const int g = lane >> 3, r = lane & 7;
    const int a_m = ((g & 1) << 3) + r;
    const int a_k = (g >> 1) << 3;
    const int b_n = ((g >> 1) << 3) + r;
    const int b_k = (g & 1) << 3;

#pragma unroll
    for (int j = 0; j < 8; j++) {
        const int idx = t + j * 128;
        const int row = idx >> 3, q = idx & 7;
        *(uint4*)(GH + row * 144 + q * 16) = *(const uint4*)&g_GD[(wb * 128 + row) * 64 + q * 8];
    }
    __syncthreads();

    const int M0 = warp * 32;
    uint32_t gh[4][2][4];
#pragma unroll
    for (int ks = 0; ks < 4; ks++)
#pragma unroll
        for (int t2 = 0; t2 < 2; t2++)
            ldmx4(gh[ks][t2],
                  GHb + (uint32_t)((M0 + 16 * t2 + a_m) * 144 + (ks * 16 + a_k) * 2));

    const int cq = lane >> 2, f2 = (lane & 3) * 2;
    for (int hh = 0; hh < 32; hh++) {
        const int h = hg * 32 + hh;
        const size_t zb = (size_t)(b * 1024 + h) * 2048;
        __syncthreads();
#pragma unroll
        for (int j = 0; j < 2; j++) {                 // 256 uint4
            const int idx = t + j * 128;
            const int row = idx >> 3, q = idx & 7;
            *(uint4*)(ZH + row * 144 + q * 16) = *(const uint4*)&g_Zh[zb + row * 64 + q * 8];
        }
        __syncthreads();
        float acc[2][4][4];
#pragma unroll
        for (int i = 0; i < 2; i++)
#pragma unroll
            for (int j = 0; j < 4; j++)
#pragma unroll
                for (int q = 0; q < 4; q++) acc[i][j][q] = 0.f;
#pragma unroll
        for (int ks = 0; ks < 4; ks++) {
#pragma unroll
            for (int jn = 0; jn < 2; jn++) {
                uint32_t bh[4];
                ldmx4(bh, ZHb + (uint32_t)((jn * 16 + b_n) * 144 + (ks * 16 + b_k) * 2));
#pragma unroll
                for (int t2 = 0; t2 < 2; t2++) {
                    mma_f16(acc[t2][2 * jn],     gh[ks][t2], bh);
                    mma_f16(acc[t2][2 * jn + 1], gh[ks][t2], bh + 2);
                }
            }
        }
        float* yb = y + (size_t)(b * 1024 + h) * 32768;
#pragma unroll
        for (int t2 = 0; t2 < 2; t2++)
#pragma unroll
            for (int j = 0; j < 4; j++) {
                const int w = wb * 128 + M0 + 16 * t2 + cq;
                const int c = 8 * j + f2;
                *(float2*)&yb[(size_t)w * 32 + c] =
                    make_float2(acc[t2][j][0], acc[t2][j][1]);
                *(float2*)&yb[(size_t)(w + 8) * 32 + c] =
                    make_float2(acc[t2][j][2], acc[t2][j][3]);
            }
    }
}

// ---------------------------------------------------------------------------
extern "C" void kernel_launch(void* const* d_in, const int* in_sizes, int n_in,
                              void* d_out, int out_size) {
    const float* x   = (const float*)d_in[0];
    const float* w0r = (const float*)d_in[1];
    const float* w0i = (const float*)d_in[2];
    const float* w1r = (const float*)d_in[3];
    const float* w1i = (const float*)d_in[4];
    const float* w2r = (const float*)d_in[5];
    const float* w2i = (const float*)d_in[6];
    float* y = (float*)d_out;

    k_init_tables<<<1024, 64>>>();
    k_init_w<<<256, 256>>>(w0r, w0i, w1r, w1i, w2r, w2i);
    kTA<<<dim3(256, 2), 128>>>(x);
    kB<<<dim3(16, 16, 2), 256>>>();
    k_reduce_w<<<512, 256>>>();
    kC<<<dim3(32, 16, 2), 256>>>();
    kTD<<<dim3(8, 32, 2), 128>>>(y);
}